// round 2
// baseline (speedup 1.0000x reference)
#include <cuda_runtime.h>

// MaskedNorm: X[B,N,D] fp32, mask[B,N] (True == masked out), W[D], b[D].
// out = mask ? (0*W + b) : (X - mean_n)/std_n * W + b   (std unbiased, ddof=1)
#define Bz 64
#define Nz 8192
#define Dz 128
#define D4 32          // D/4 float4 lanes
#define SPLITS 16      // stats blocks per batch
#define ROWS_PER_SPLIT (Nz / SPLITS)   // 512
#define RPB 128        // rows per block in normalize kernel

__device__ float g_sum[Bz * Dz];
__device__ float g_sq[Bz * Dz];
__device__ int   g_cnt[Bz];

__global__ void mn_zero_kernel() {
    int i = blockIdx.x * blockDim.x + threadIdx.x;
    if (i < Bz * Dz) { g_sum[i] = 0.f; g_sq[i] = 0.f; }
    if (i < Bz) g_cnt[i] = 0;
}

// grid (SPLITS, B), block 256.  warp w handles rows row0+w, row0+w+8, ...
__global__ void mn_stats_kernel(const float* __restrict__ X,
                                const int* __restrict__ mask) {
    const int b     = blockIdx.y;
    const int split = blockIdx.x;
    const int tid   = threadIdx.x;
    const int d4    = tid & 31;    // float4 lane in D
    const int rg    = tid >> 5;    // row group 0..7 (== warp id)
    const int row0  = split * ROWS_PER_SPLIT;

    const float4* Xb = (const float4*)(X + (size_t)b * Nz * Dz);
    const int*    mb = mask + (size_t)b * Nz;

    float4 s = make_float4(0.f, 0.f, 0.f, 0.f);
    float4 q = make_float4(0.f, 0.f, 0.f, 0.f);
    int cnt = 0;

    for (int r = row0 + rg; r < row0 + ROWS_PER_SPLIT; r += 8) {
        int m = mb[r];                         // uniform per warp (broadcast)
        if (!m) {
            float4 v = Xb[(size_t)r * D4 + d4];
            s.x += v.x; s.y += v.y; s.z += v.z; s.w += v.w;
            q.x += v.x * v.x; q.y += v.y * v.y;
            q.z += v.z * v.z; q.w += v.w * v.w;
            cnt++;
        }
    }

    __shared__ float ssum[8][Dz];
    __shared__ float ssq[8][Dz];
    __shared__ int   scnt[8];
    ((float4*)&ssum[rg][0])[d4] = s;
    ((float4*)&ssq[rg][0])[d4]  = q;
    if (d4 == 0) scnt[rg] = cnt;
    __syncthreads();

    if (tid < Dz) {
        float ts = 0.f, tq = 0.f;
        #pragma unroll
        for (int i = 0; i < 8; i++) { ts += ssum[i][tid]; tq += ssq[i][tid]; }
        atomicAdd(&g_sum[b * Dz + tid], ts);
        atomicAdd(&g_sq[b * Dz + tid], tq);
    }
    if (tid == 0) {
        int c = 0;
        #pragma unroll
        for (int i = 0; i < 8; i++) c += scnt[i];
        atomicAdd(&g_cnt[b], c);
    }
}

// grid (N/RPB, B), block 256.
__global__ void mn_norm_kernel(const float* __restrict__ X,
                               const int* __restrict__ mask,
                               const float* __restrict__ W,
                               const float* __restrict__ bias,
                               float* __restrict__ out) {
    const int b   = blockIdx.y;
    const int tid = threadIdx.x;

    __shared__ float sa[Dz];   // W * invstd
    __shared__ float sc[Dz];   // bias - mean * W * invstd
    __shared__ float sb[Dz];   // replace value: 0*W + bias

    if (tid < Dz) {
        float c    = (float)g_cnt[b];
        float mean = g_sum[b * Dz + tid] / c;
        float var  = (g_sq[b * Dz + tid] - c * mean * mean) / (c - 1.0f);
        float inv  = rsqrtf(var);
        float w    = W[tid];
        float bb   = bias[tid];
        float a    = w * inv;
        sa[tid] = a;
        sc[tid] = bb - mean * a;
        sb[tid] = 0.0f * w + bb;
    }
    __syncthreads();

    const int d4   = tid & 31;
    const int rg   = tid >> 5;
    const int row0 = blockIdx.x * RPB;
    const int dd   = d4 * 4;

    const float4* Xb = (const float4*)(X + (size_t)b * Nz * Dz);
    float4*       Ob = (float4*)(out + (size_t)b * Nz * Dz);
    const int*    mb = mask + (size_t)b * Nz;

    float a0 = sa[dd], a1 = sa[dd + 1], a2 = sa[dd + 2], a3 = sa[dd + 3];
    float c0 = sc[dd], c1 = sc[dd + 1], c2 = sc[dd + 2], c3 = sc[dd + 3];
    float r0 = sb[dd], r1 = sb[dd + 1], r2 = sb[dd + 2], r3 = sb[dd + 3];

    for (int r = row0 + rg; r < row0 + RPB; r += 8) {
        int m = mb[r];
        float4 v = Xb[(size_t)r * D4 + d4];
        float4 o;
        if (m) {
            o.x = r0; o.y = r1; o.z = r2; o.w = r3;
        } else {
            o.x = fmaf(v.x, a0, c0);
            o.y = fmaf(v.y, a1, c1);
            o.z = fmaf(v.z, a2, c2);
            o.w = fmaf(v.w, a3, c3);
        }
        Ob[(size_t)r * D4 + d4] = o;
    }
}

extern "C" void kernel_launch(void* const* d_in, const int* in_sizes, int n_in,
                              void* d_out, int out_size) {
    const float* X    = (const float*)d_in[0];
    const int*   mask = (const int*)d_in[1];
    const float* W    = (const float*)d_in[2];
    const float* bias = (const float*)d_in[3];
    float* out        = (float*)d_out;

    mn_zero_kernel<<<(Bz * Dz + 255) / 256, 256>>>();

    dim3 g1(SPLITS, Bz);
    mn_stats_kernel<<<g1, 256>>>(X, mask);

    dim3 g2(Nz / RPB, Bz);
    mn_norm_kernel<<<g2, 256>>>(X, mask, W, bias, out);
}

// round 4
// speedup vs baseline: 1.0590x; 1.0590x over previous
#include <cuda_runtime.h>

// MaskedNorm: X[B,N,D] fp32, mask[B,N] int32 (1 == masked out), W[D], b[D].
// out = mask ? b : (X - mean_n)/std_n * W + b   (std unbiased, ddof=1; REPLACE=0)
#define Bz 64
#define Nz 8192
#define Dz 128
#define D4 32          // D/4 float4 lanes
#define SPLITS 16      // stats blocks per batch
#define ROWS_PER_SPLIT (Nz / SPLITS)   // 512
#define RPB 256        // rows per block in normalize kernel

__device__ float g_sum[Bz * Dz];
__device__ float g_sq[Bz * Dz];
__device__ int   g_cnt[Bz];

__global__ void mn_zero_kernel() {
    int i = blockIdx.x * blockDim.x + threadIdx.x;
    if (i < Bz * Dz) { g_sum[i] = 0.f; g_sq[i] = 0.f; }
    if (i < Bz) g_cnt[i] = 0;
}

// grid (SPLITS, B), block 256.  warp w handles rows row0+w, row0+w+8, ...
__global__ void mn_stats_kernel(const float* __restrict__ X,
                                const int* __restrict__ mask) {
    const int b     = blockIdx.y;
    const int split = blockIdx.x;
    const int tid   = threadIdx.x;
    const int d4    = tid & 31;    // float4 lane in D
    const int rg    = tid >> 5;    // row group 0..7 (== warp id)
    const int row0  = split * ROWS_PER_SPLIT;

    const float4* Xb = (const float4*)(X + (size_t)b * Nz * Dz);
    const int*    mb = mask + (size_t)b * Nz;

    float4 s = make_float4(0.f, 0.f, 0.f, 0.f);
    float4 q = make_float4(0.f, 0.f, 0.f, 0.f);
    int cnt = 0;

    for (int r = row0 + rg; r < row0 + ROWS_PER_SPLIT; r += 8) {
        int m = mb[r];                         // uniform per warp (broadcast)
        if (!m) {
            float4 v = Xb[(size_t)r * D4 + d4];
            s.x += v.x; s.y += v.y; s.z += v.z; s.w += v.w;
            q.x = fmaf(v.x, v.x, q.x); q.y = fmaf(v.y, v.y, q.y);
            q.z = fmaf(v.z, v.z, q.z); q.w = fmaf(v.w, v.w, q.w);
            cnt++;
        }
    }

    __shared__ float ssum[8][Dz];
    __shared__ float ssq[8][Dz];
    __shared__ int   scnt[8];
    ((float4*)&ssum[rg][0])[d4] = s;
    ((float4*)&ssq[rg][0])[d4]  = q;
    if (d4 == 0) scnt[rg] = cnt;
    __syncthreads();

    if (tid < Dz) {
        float ts = 0.f, tq = 0.f;
        #pragma unroll
        for (int i = 0; i < 8; i++) { ts += ssum[i][tid]; tq += ssq[i][tid]; }
        atomicAdd(&g_sum[b * Dz + tid], ts);
        atomicAdd(&g_sq[b * Dz + tid], tq);
    }
    if (tid == 0) {
        int c = 0;
        #pragma unroll
        for (int i = 0; i < 8; i++) c += scnt[i];
        atomicAdd(&g_cnt[b], c);
    }
}

// grid (N/RPB, B), block 256.
__global__ void mn_norm_kernel(const float* __restrict__ X,
                               const int* __restrict__ mask,
                               const float* __restrict__ W,
                               const float* __restrict__ bias,
                               float* __restrict__ out) {
    const int b   = blockIdx.y;
    const int tid = threadIdx.x;

    __shared__ float sa[Dz];   // W * invstd
    __shared__ float sc[Dz];   // bias - mean * W * invstd
    __shared__ float sr[Dz];   // replacement value: 0*W + bias

    if (tid < Dz) {
        float c    = (float)g_cnt[b];
        float mean = g_sum[b * Dz + tid] / c;
        float var  = (g_sq[b * Dz + tid] - c * mean * mean) / (c - 1.0f);
        float inv  = rsqrtf(var);
        float w    = W[tid];
        float bb   = bias[tid];
        float a    = w * inv;
        sa[tid] = a;
        sc[tid] = bb - mean * a;
        sr[tid] = bb;
    }
    __syncthreads();

    const int d4   = tid & 31;
    const int rg   = tid >> 5;
    const int row0 = blockIdx.x * RPB;
    const int dd   = d4 * 4;

    const float4* Xb = (const float4*)(X + (size_t)b * Nz * Dz);
    float4*       Ob = (float4*)(out + (size_t)b * Nz * Dz);
    const int*    mb = mask + (size_t)b * Nz;

    const float a0 = sa[dd], a1 = sa[dd + 1], a2 = sa[dd + 2], a3 = sa[dd + 3];
    const float c0 = sc[dd], c1 = sc[dd + 1], c2 = sc[dd + 2], c3 = sc[dd + 3];
    float4 rv;
    rv.x = sr[dd]; rv.y = sr[dd + 1]; rv.z = sr[dd + 2]; rv.w = sr[dd + 3];

    // 32 rows per warp, unroll 4 with mask prefetch.
    // X is loaded ONLY for valid rows; masked rows store the replacement vector.
    for (int r = row0 + rg; r < row0 + RPB; r += 32) {
        const int m0 = mb[r];
        const int m1 = mb[r + 8];
        const int m2 = mb[r + 16];
        const int m3 = mb[r + 24];

        if (m0) {
            Ob[(size_t)r * D4 + d4] = rv;
        } else {
            float4 v = Xb[(size_t)r * D4 + d4];
            float4 o;
            o.x = fmaf(v.x, a0, c0); o.y = fmaf(v.y, a1, c1);
            o.z = fmaf(v.z, a2, c2); o.w = fmaf(v.w, a3, c3);
            Ob[(size_t)r * D4 + d4] = o;
        }
        if (m1) {
            Ob[(size_t)(r + 8) * D4 + d4] = rv;
        } else {
            float4 v = Xb[(size_t)(r + 8) * D4 + d4];
            float4 o;
            o.x = fmaf(v.x, a0, c0); o.y = fmaf(v.y, a1, c1);
            o.z = fmaf(v.z, a2, c2); o.w = fmaf(v.w, a3, c3);
            Ob[(size_t)(r + 8) * D4 + d4] = o;
        }
        if (m2) {
            Ob[(size_t)(r + 16) * D4 + d4] = rv;
        } else {
            float4 v = Xb[(size_t)(r + 16) * D4 + d4];
            float4 o;
            o.x = fmaf(v.x, a0, c0); o.y = fmaf(v.y, a1, c1);
            o.z = fmaf(v.z, a2, c2); o.w = fmaf(v.w, a3, c3);
            Ob[(size_t)(r + 16) * D4 + d4] = o;
        }
        if (m3) {
            Ob[(size_t)(r + 24) * D4 + d4] = rv;
        } else {
            float4 v = Xb[(size_t)(r + 24) * D4 + d4];
            float4 o;
            o.x = fmaf(v.x, a0, c0); o.y = fmaf(v.y, a1, c1);
            o.z = fmaf(v.z, a2, c2); o.w = fmaf(v.w, a3, c3);
            Ob[(size_t)(r + 24) * D4 + d4] = o;
        }
    }
}

extern "C" void kernel_launch(void* const* d_in, const int* in_sizes, int n_in,
                              void* d_out, int out_size) {
    const float* X    = (const float*)d_in[0];
    const int*   mask = (const int*)d_in[1];
    const float* W    = (const float*)d_in[2];
    const float* bias = (const float*)d_in[3];
    float* out        = (float*)d_out;

    mn_zero_kernel<<<(Bz * Dz + 255) / 256, 256>>>();

    dim3 g1(SPLITS, Bz);
    mn_stats_kernel<<<g1, 256>>>(X, mask);

    dim3 g2(Nz / RPB, Bz);
    mn_norm_kernel<<<g2, 256>>>(X, mask, W, bias, out);
}

// round 6
// speedup vs baseline: 1.0623x; 1.0031x over previous
#include <cuda_runtime.h>

// MaskedNorm: X[B,N,D] fp32, mask[B,N] int32 (1 == masked out), W[D], b[D].
// out = mask ? b : (X - mean_n)/std_n * W + b   (std unbiased, ddof=1; REPLACE=0)
#define Bz 64
#define Nz 8192
#define Dz 128
#define D4 32          // D/4 float4 lanes
#define SPLITS 16      // stats blocks per batch
#define ROWS_PER_SPLIT (Nz / SPLITS)   // 512
#define RPB 256        // rows per block in normalize kernel

__device__ float g_sum[Bz * Dz];
__device__ float g_sq[Bz * Dz];
__device__ int   g_cnt[Bz];

__global__ void mn_zero_kernel() {
    int i = blockIdx.x * blockDim.x + threadIdx.x;
    if (i < Bz * Dz) { g_sum[i] = 0.f; g_sq[i] = 0.f; }
    if (i < Bz) g_cnt[i] = 0;
}

// grid (SPLITS, B), block 256.  warp w handles rows row0+w, row0+w+8, ...
// Warp-uniform skip of masked rows (saves DRAM reads; proven at-ceiling in R2).
__global__ void mn_stats_kernel(const float* __restrict__ X,
                                const int* __restrict__ mask) {
    const int b     = blockIdx.y;
    const int split = blockIdx.x;
    const int tid   = threadIdx.x;
    const int d4    = tid & 31;    // float4 lane in D
    const int rg    = tid >> 5;    // row group 0..7 (== warp id)
    const int row0  = split * ROWS_PER_SPLIT;

    const float4* Xb = (const float4*)(X + (size_t)b * Nz * Dz);
    const int*    mb = mask + (size_t)b * Nz;

    float4 s = make_float4(0.f, 0.f, 0.f, 0.f);
    float4 q = make_float4(0.f, 0.f, 0.f, 0.f);
    int cnt = 0;

    for (int r = row0 + rg; r < row0 + ROWS_PER_SPLIT; r += 8) {
        int m = mb[r];                         // uniform per warp (broadcast)
        if (!m) {
            float4 v = Xb[(size_t)r * D4 + d4];
            s.x += v.x; s.y += v.y; s.z += v.z; s.w += v.w;
            q.x = fmaf(v.x, v.x, q.x); q.y = fmaf(v.y, v.y, q.y);
            q.z = fmaf(v.z, v.z, q.z); q.w = fmaf(v.w, v.w, q.w);
            cnt++;
        }
    }

    __shared__ float ssum[8][Dz];
    __shared__ float ssq[8][Dz];
    __shared__ int   scnt[8];
    ((float4*)&ssum[rg][0])[d4] = s;
    ((float4*)&ssq[rg][0])[d4]  = q;
    if (d4 == 0) scnt[rg] = cnt;
    __syncthreads();

    if (tid < Dz) {
        float ts = 0.f, tq = 0.f;
        #pragma unroll
        for (int i = 0; i < 8; i++) { ts += ssum[i][tid]; tq += ssq[i][tid]; }
        atomicAdd(&g_sum[b * Dz + tid], ts);
        atomicAdd(&g_sq[b * Dz + tid], tq);
    }
    if (tid == 0) {
        int c = 0;
        #pragma unroll
        for (int i = 0; i < 8; i++) c += scnt[i];
        atomicAdd(&g_cnt[b], c);
    }
}

// grid (N/RPB, B), block 256.
// Branch-free mainloop: loads ALWAYS issue (masked rows redirected to the
// always-hot row 0 of this batch -> L2 hit, no DRAM), outputs selected via FSEL.
__global__ void mn_norm_kernel(const float* __restrict__ X,
                               const int* __restrict__ mask,
                               const float* __restrict__ W,
                               const float* __restrict__ bias,
                               float* __restrict__ out) {
    const int b   = blockIdx.y;
    const int tid = threadIdx.x;

    __shared__ float sa[Dz];   // W * invstd
    __shared__ float sc[Dz];   // bias - mean * W * invstd
    __shared__ float sr[Dz];   // replacement value: 0*W + bias

    if (tid < Dz) {
        float c    = (float)g_cnt[b];
        float mean = g_sum[b * Dz + tid] / c;
        float var  = (g_sq[b * Dz + tid] - c * mean * mean) / (c - 1.0f);
        float inv  = rsqrtf(var);
        float w    = W[tid];
        float bb   = bias[tid];
        float a    = w * inv;
        sa[tid] = a;
        sc[tid] = bb - mean * a;
        sr[tid] = bb;
    }
    __syncthreads();

    const int d4   = tid & 31;
    const int rg   = tid >> 5;
    const int row0 = blockIdx.x * RPB;
    const int dd   = d4 * 4;

    const float4* Xb = (const float4*)(X + (size_t)b * Nz * Dz);
    float4*       Ob = (float4*)(out + (size_t)b * Nz * Dz);
    const int*    mb = mask + (size_t)b * Nz;

    const float a0 = sa[dd], a1 = sa[dd + 1], a2 = sa[dd + 2], a3 = sa[dd + 3];
    const float c0 = sc[dd], c1 = sc[dd + 1], c2 = sc[dd + 2], c3 = sc[dd + 3];
    float4 rv;
    rv.x = sr[dd]; rv.y = sr[dd + 1]; rv.z = sr[dd + 2]; rv.w = sr[dd + 3];

    // 32 rows per warp, unroll 4.  All loads unconditional (full MLP); masked
    // rows read batch row 0 (512B, L2-hot) so they cost no DRAM bandwidth.
    for (int r = row0 + rg; r < row0 + RPB; r += 32) {
        const int rA = r, rB = r + 8, rC = r + 16, rD = r + 24;
        const int m0 = mb[rA];
        const int m1 = mb[rB];
        const int m2 = mb[rC];
        const int m3 = mb[rD];

        const size_t i0 = m0 ? (size_t)d4 : (size_t)rA * D4 + d4;
        const size_t i1 = m1 ? (size_t)d4 : (size_t)rB * D4 + d4;
        const size_t i2 = m2 ? (size_t)d4 : (size_t)rC * D4 + d4;
        const size_t i3 = m3 ? (size_t)d4 : (size_t)rD * D4 + d4;

        const float4 v0 = Xb[i0];
        const float4 v1 = Xb[i1];
        const float4 v2 = Xb[i2];
        const float4 v3 = Xb[i3];

        float4 o0, o1, o2, o3;
        o0.x = m0 ? rv.x : fmaf(v0.x, a0, c0);
        o0.y = m0 ? rv.y : fmaf(v0.y, a1, c1);
        o0.z = m0 ? rv.z : fmaf(v0.z, a2, c2);
        o0.w = m0 ? rv.w : fmaf(v0.w, a3, c3);

        o1.x = m1 ? rv.x : fmaf(v1.x, a0, c0);
        o1.y = m1 ? rv.y : fmaf(v1.y, a1, c1);
        o1.z = m1 ? rv.z : fmaf(v1.z, a2, c2);
        o1.w = m1 ? rv.w : fmaf(v1.w, a3, c3);

        o2.x = m2 ? rv.x : fmaf(v2.x, a0, c0);
        o2.y = m2 ? rv.y : fmaf(v2.y, a1, c1);
        o2.z = m2 ? rv.z : fmaf(v2.z, a2, c2);
        o2.w = m2 ? rv.w : fmaf(v2.w, a3, c3);

        o3.x = m3 ? rv.x : fmaf(v3.x, a0, c0);
        o3.y = m3 ? rv.y : fmaf(v3.y, a1, c1);
        o3.z = m3 ? rv.z : fmaf(v3.z, a2, c2);
        o3.w = m3 ? rv.w : fmaf(v3.w, a3, c3);

        Ob[(size_t)rA * D4 + d4] = o0;
        Ob[(size_t)rB * D4 + d4] = o1;
        Ob[(size_t)rC * D4 + d4] = o2;
        Ob[(size_t)rD * D4 + d4] = o3;
    }
}

extern "C" void kernel_launch(void* const* d_in, const int* in_sizes, int n_in,
                              void* d_out, int out_size) {
    const float* X    = (const float*)d_in[0];
    const int*   mask = (const int*)d_in[1];
    const float* W    = (const float*)d_in[2];
    const float* bias = (const float*)d_in[3];
    float* out        = (float*)d_out;

    mn_zero_kernel<<<(Bz * Dz + 255) / 256, 256>>>();

    dim3 g1(SPLITS, Bz);
    mn_stats_kernel<<<g1, 256>>>(X, mask);

    dim3 g2(Nz / RPB, Bz);
    mn_norm_kernel<<<g2, 256>>>(X, mask, W, bias, out);
}

// round 7
// speedup vs baseline: 1.1305x; 1.0643x over previous
#include <cuda_runtime.h>

// MaskedNorm: X[B,N,D] fp32, mask[B,N] int32 (1 == masked out), W[D], b[D].
// out = mask ? b : (X - mean_n)/std_n * W + b   (std unbiased, ddof=1; REPLACE=0)
#define Bz 64
#define Nz 8192
#define Dz 128
#define D4 32          // D/4 float4 lanes
#define SPLITS 16      // stats blocks per batch
#define ROWS_PER_SPLIT (Nz / SPLITS)   // 512
#define RPB 256        // rows per block in normalize kernel

__device__ float g_sum[Bz * Dz];
__device__ float g_sq[Bz * Dz];
__device__ int   g_cnt[Bz];

__global__ void mn_zero_kernel() {
    int i = blockIdx.x * blockDim.x + threadIdx.x;
    if (i < Bz * Dz) { g_sum[i] = 0.f; g_sq[i] = 0.f; }
    if (i < Bz) g_cnt[i] = 0;
}

// grid (SPLITS, B), block 256.  warp w handles rows row0+w, row0+w+8, ...
// Default load policy: valid X lines stay resident in L2 for the norm kernel.
__global__ void mn_stats_kernel(const float* __restrict__ X,
                                const int* __restrict__ mask) {
    const int b     = blockIdx.y;
    const int split = blockIdx.x;
    const int tid   = threadIdx.x;
    const int d4    = tid & 31;    // float4 lane in D
    const int rg    = tid >> 5;    // row group 0..7 (== warp id)
    const int row0  = split * ROWS_PER_SPLIT;

    const float4* Xb = (const float4*)(X + (size_t)b * Nz * Dz);
    const int*    mb = mask + (size_t)b * Nz;

    float4 s = make_float4(0.f, 0.f, 0.f, 0.f);
    float4 q = make_float4(0.f, 0.f, 0.f, 0.f);
    int cnt = 0;

    for (int r = row0 + rg; r < row0 + ROWS_PER_SPLIT; r += 8) {
        int m = mb[r];                         // uniform per warp (broadcast)
        if (!m) {
            float4 v = Xb[(size_t)r * D4 + d4];
            s.x += v.x; s.y += v.y; s.z += v.z; s.w += v.w;
            q.x = fmaf(v.x, v.x, q.x); q.y = fmaf(v.y, v.y, q.y);
            q.z = fmaf(v.z, v.z, q.z); q.w = fmaf(v.w, v.w, q.w);
            cnt++;
        }
    }

    __shared__ float ssum[8][Dz];
    __shared__ float ssq[8][Dz];
    __shared__ int   scnt[8];
    ((float4*)&ssum[rg][0])[d4] = s;
    ((float4*)&ssq[rg][0])[d4]  = q;
    if (d4 == 0) scnt[rg] = cnt;
    __syncthreads();

    if (tid < Dz) {
        float ts = 0.f, tq = 0.f;
        #pragma unroll
        for (int i = 0; i < 8; i++) { ts += ssum[i][tid]; tq += ssq[i][tid]; }
        atomicAdd(&g_sum[b * Dz + tid], ts);
        atomicAdd(&g_sq[b * Dz + tid], tq);
    }
    if (tid == 0) {
        int c = 0;
        #pragma unroll
        for (int i = 0; i < 8; i++) c += scnt[i];
        atomicAdd(&g_cnt[b], c);
    }
}

// grid (N/RPB, B), block 256.
// LIFO batch traversal (b = Bz-1 - blockIdx.y): consumes the L2-resident tail
// of the stats kernel's read set first.  Loads use .cs (dead after read),
// stores use .cs (evict-first; don't pollute the warm stats lines).
__global__ void mn_norm_kernel(const float* __restrict__ X,
                               const int* __restrict__ mask,
                               const float* __restrict__ W,
                               const float* __restrict__ bias,
                               float* __restrict__ out) {
    const int b   = Bz - 1 - blockIdx.y;    // reverse: most-recently-warmed first
    const int tid = threadIdx.x;

    __shared__ float sa[Dz];   // W * invstd
    __shared__ float sc[Dz];   // bias - mean * W * invstd
    __shared__ float sr[Dz];   // replacement value: 0*W + bias

    if (tid < Dz) {
        float c    = (float)g_cnt[b];
        float mean = g_sum[b * Dz + tid] / c;
        float var  = (g_sq[b * Dz + tid] - c * mean * mean) / (c - 1.0f);
        float inv  = rsqrtf(var);
        float w    = W[tid];
        float bb   = bias[tid];
        float a    = w * inv;
        sa[tid] = a;
        sc[tid] = bb - mean * a;
        sr[tid] = bb;
    }
    __syncthreads();

    const int d4   = tid & 31;
    const int rg   = tid >> 5;
    const int row0 = blockIdx.x * RPB;
    const int dd   = d4 * 4;

    const float4* Xb = (const float4*)(X + (size_t)b * Nz * Dz);
    float4*       Ob = (float4*)(out + (size_t)b * Nz * Dz);
    const int*    mb = mask + (size_t)b * Nz;

    const float a0 = sa[dd], a1 = sa[dd + 1], a2 = sa[dd + 2], a3 = sa[dd + 3];
    const float c0 = sc[dd], c1 = sc[dd + 1], c2 = sc[dd + 2], c3 = sc[dd + 3];
    float4 rv;
    rv.x = sr[dd]; rv.y = sr[dd + 1]; rv.z = sr[dd + 2]; rv.w = sr[dd + 3];

    // 32 rows per warp, unroll 4.  All loads unconditional (full MLP); masked
    // rows read batch row 0 (512B, always hot) so they cost no DRAM bandwidth.
    for (int r = row0 + rg; r < row0 + RPB; r += 32) {
        const int rA = r, rB = r + 8, rC = r + 16, rD = r + 24;
        const int m0 = mb[rA];
        const int m1 = mb[rB];
        const int m2 = mb[rC];
        const int m3 = mb[rD];

        const size_t i0 = m0 ? (size_t)d4 : (size_t)rA * D4 + d4;
        const size_t i1 = m1 ? (size_t)d4 : (size_t)rB * D4 + d4;
        const size_t i2 = m2 ? (size_t)d4 : (size_t)rC * D4 + d4;
        const size_t i3 = m3 ? (size_t)d4 : (size_t)rD * D4 + d4;

        const float4 v0 = __ldcs(&Xb[i0]);
        const float4 v1 = __ldcs(&Xb[i1]);
        const float4 v2 = __ldcs(&Xb[i2]);
        const float4 v3 = __ldcs(&Xb[i3]);

        float4 o0, o1, o2, o3;
        o0.x = m0 ? rv.x : fmaf(v0.x, a0, c0);
        o0.y = m0 ? rv.y : fmaf(v0.y, a1, c1);
        o0.z = m0 ? rv.z : fmaf(v0.z, a2, c2);
        o0.w = m0 ? rv.w : fmaf(v0.w, a3, c3);

        o1.x = m1 ? rv.x : fmaf(v1.x, a0, c0);
        o1.y = m1 ? rv.y : fmaf(v1.y, a1, c1);
        o1.z = m1 ? rv.z : fmaf(v1.z, a2, c2);
        o1.w = m1 ? rv.w : fmaf(v1.w, a3, c3);

        o2.x = m2 ? rv.x : fmaf(v2.x, a0, c0);
        o2.y = m2 ? rv.y : fmaf(v2.y, a1, c1);
        o2.z = m2 ? rv.z : fmaf(v2.z, a2, c2);
        o2.w = m2 ? rv.w : fmaf(v2.w, a3, c3);

        o3.x = m3 ? rv.x : fmaf(v3.x, a0, c0);
        o3.y = m3 ? rv.y : fmaf(v3.y, a1, c1);
        o3.z = m3 ? rv.z : fmaf(v3.z, a2, c2);
        o3.w = m3 ? rv.w : fmaf(v3.w, a3, c3);

        __stcs(&Ob[(size_t)rA * D4 + d4], o0);
        __stcs(&Ob[(size_t)rB * D4 + d4], o1);
        __stcs(&Ob[(size_t)rC * D4 + d4], o2);
        __stcs(&Ob[(size_t)rD * D4 + d4], o3);
    }
}

extern "C" void kernel_launch(void* const* d_in, const int* in_sizes, int n_in,
                              void* d_out, int out_size) {
    const float* X    = (const float*)d_in[0];
    const int*   mask = (const int*)d_in[1];
    const float* W    = (const float*)d_in[2];
    const float* bias = (const float*)d_in[3];
    float* out        = (float*)d_out;

    mn_zero_kernel<<<(Bz * Dz + 255) / 256, 256>>>();

    dim3 g1(SPLITS, Bz);
    mn_stats_kernel<<<g1, 256>>>(X, mask);

    dim3 g2(Nz / RPB, Bz);
    mn_norm_kernel<<<g2, 256>>>(X, mask, W, bias, out);
}

// round 8
// speedup vs baseline: 1.1821x; 1.0456x over previous
#include <cuda_runtime.h>

// MaskedNorm: X[B,N,D] fp32, mask[B,N] int32 (1 == masked out), W[D], b[D].
// out = mask ? b : (X - mean_n)/std_n * W + b   (std unbiased, ddof=1; REPLACE=0)
#define Bz 64
#define Nz 8192
#define Dz 128
#define D4 32          // D/4 float4 lanes
#define SPLITS 16      // stats blocks per batch
#define ROWS_PER_SPLIT (Nz / SPLITS)   // 512
#define RPB 256        // rows per block in normalize kernel

// Per-split partials: every slot is overwritten on every launch.
// -> no zero kernel, no atomics, deterministic under graph replay.
__device__ float g_psum[SPLITS][Bz * Dz];
__device__ float g_psq [SPLITS][Bz * Dz];
__device__ int   g_pcnt[SPLITS][Bz];

// grid (SPLITS, B), block 256.  warp w handles rows row0+w, row0+w+8, ...
// Default load policy: valid X lines stay resident in L2 for the norm kernel.
__global__ void mn_stats_kernel(const float* __restrict__ X,
                                const int* __restrict__ mask) {
    const int b     = blockIdx.y;
    const int split = blockIdx.x;
    const int tid   = threadIdx.x;
    const int d4    = tid & 31;    // float4 lane in D
    const int rg    = tid >> 5;    // row group 0..7 (== warp id)
    const int row0  = split * ROWS_PER_SPLIT;

    const float4* Xb = (const float4*)(X + (size_t)b * Nz * Dz);
    const int*    mb = mask + (size_t)b * Nz;

    float4 s = make_float4(0.f, 0.f, 0.f, 0.f);
    float4 q = make_float4(0.f, 0.f, 0.f, 0.f);
    int cnt = 0;

    for (int r = row0 + rg; r < row0 + ROWS_PER_SPLIT; r += 8) {
        int m = mb[r];                         // uniform per warp (broadcast)
        if (!m) {
            float4 v = Xb[(size_t)r * D4 + d4];
            s.x += v.x; s.y += v.y; s.z += v.z; s.w += v.w;
            q.x = fmaf(v.x, v.x, q.x); q.y = fmaf(v.y, v.y, q.y);
            q.z = fmaf(v.z, v.z, q.z); q.w = fmaf(v.w, v.w, q.w);
            cnt++;
        }
    }

    __shared__ float ssum[8][Dz];
    __shared__ float ssq[8][Dz];
    __shared__ int   scnt[8];
    ((float4*)&ssum[rg][0])[d4] = s;
    ((float4*)&ssq[rg][0])[d4]  = q;
    if (d4 == 0) scnt[rg] = cnt;
    __syncthreads();

    if (tid < Dz) {
        float ts = 0.f, tq = 0.f;
        #pragma unroll
        for (int i = 0; i < 8; i++) { ts += ssum[i][tid]; tq += ssq[i][tid]; }
        g_psum[split][b * Dz + tid] = ts;      // plain store, overwritten every launch
        g_psq [split][b * Dz + tid] = tq;
    }
    if (tid == 0) {
        int c = 0;
        #pragma unroll
        for (int i = 0; i < 8; i++) c += scnt[i];
        g_pcnt[split][b] = c;
    }
}

// grid (N/RPB, B), block 256.
// LIFO batch traversal (b = Bz-1 - blockIdx.y): consumes the L2-resident tail
// of the stats kernel's read set first.  Loads use .cs (dead after read),
// stores use .cs (evict-first; don't pollute the warm stats lines).
__global__ void mn_norm_kernel(const float* __restrict__ X,
                               const int* __restrict__ mask,
                               const float* __restrict__ W,
                               const float* __restrict__ bias,
                               float* __restrict__ out) {
    const int b   = Bz - 1 - blockIdx.y;    // reverse: most-recently-warmed first
    const int tid = threadIdx.x;

    __shared__ float sa[Dz];   // W * invstd
    __shared__ float sc[Dz];   // bias - mean * W * invstd
    __shared__ float sr[Dz];   // replacement value: 0*W + bias

    if (tid < Dz) {
        float ts = 0.f, tq = 0.f;
        int   c  = 0;
        #pragma unroll
        for (int s = 0; s < SPLITS; s++) {
            ts += g_psum[s][b * Dz + tid];
            tq += g_psq [s][b * Dz + tid];
            c  += g_pcnt[s][b];
        }
        float fc   = (float)c;
        float mean = ts / fc;
        float var  = (tq - fc * mean * mean) / (fc - 1.0f);
        float inv  = rsqrtf(var);
        float w    = W[tid];
        float bb   = bias[tid];
        float a    = w * inv;
        sa[tid] = a;
        sc[tid] = bb - mean * a;
        sr[tid] = bb;
    }
    __syncthreads();

    const int d4   = tid & 31;
    const int rg   = tid >> 5;
    const int row0 = blockIdx.x * RPB;
    const int dd   = d4 * 4;

    const float4* Xb = (const float4*)(X + (size_t)b * Nz * Dz);
    float4*       Ob = (float4*)(out + (size_t)b * Nz * Dz);
    const int*    mb = mask + (size_t)b * Nz;

    const float a0 = sa[dd], a1 = sa[dd + 1], a2 = sa[dd + 2], a3 = sa[dd + 3];
    const float c0 = sc[dd], c1 = sc[dd + 1], c2 = sc[dd + 2], c3 = sc[dd + 3];
    float4 rv;
    rv.x = sr[dd]; rv.y = sr[dd + 1]; rv.z = sr[dd + 2]; rv.w = sr[dd + 3];

    // 32 rows per warp, unroll 4.  All loads unconditional (full MLP); masked
    // rows read batch row 0 (512B, always hot) so they cost no DRAM bandwidth.
    for (int r = row0 + rg; r < row0 + RPB; r += 32) {
        const int rA = r, rB = r + 8, rC = r + 16, rD = r + 24;
        const int m0 = mb[rA];
        const int m1 = mb[rB];
        const int m2 = mb[rC];
        const int m3 = mb[rD];

        const size_t i0 = m0 ? (size_t)d4 : (size_t)rA * D4 + d4;
        const size_t i1 = m1 ? (size_t)d4 : (size_t)rB * D4 + d4;
        const size_t i2 = m2 ? (size_t)d4 : (size_t)rC * D4 + d4;
        const size_t i3 = m3 ? (size_t)d4 : (size_t)rD * D4 + d4;

        const float4 v0 = __ldcs(&Xb[i0]);
        const float4 v1 = __ldcs(&Xb[i1]);
        const float4 v2 = __ldcs(&Xb[i2]);
        const float4 v3 = __ldcs(&Xb[i3]);

        float4 o0, o1, o2, o3;
        o0.x = m0 ? rv.x : fmaf(v0.x, a0, c0);
        o0.y = m0 ? rv.y : fmaf(v0.y, a1, c1);
        o0.z = m0 ? rv.z : fmaf(v0.z, a2, c2);
        o0.w = m0 ? rv.w : fmaf(v0.w, a3, c3);

        o1.x = m1 ? rv.x : fmaf(v1.x, a0, c0);
        o1.y = m1 ? rv.y : fmaf(v1.y, a1, c1);
        o1.z = m1 ? rv.z : fmaf(v1.z, a2, c2);
        o1.w = m1 ? rv.w : fmaf(v1.w, a3, c3);

        o2.x = m2 ? rv.x : fmaf(v2.x, a0, c0);
        o2.y = m2 ? rv.y : fmaf(v2.y, a1, c1);
        o2.z = m2 ? rv.z : fmaf(v2.z, a2, c2);
        o2.w = m2 ? rv.w : fmaf(v2.w, a3, c3);

        o3.x = m3 ? rv.x : fmaf(v3.x, a0, c0);
        o3.y = m3 ? rv.y : fmaf(v3.y, a1, c1);
        o3.z = m3 ? rv.z : fmaf(v3.z, a2, c2);
        o3.w = m3 ? rv.w : fmaf(v3.w, a3, c3);

        __stcs(&Ob[(size_t)rA * D4 + d4], o0);
        __stcs(&Ob[(size_t)rB * D4 + d4], o1);
        __stcs(&Ob[(size_t)rC * D4 + d4], o2);
        __stcs(&Ob[(size_t)rD * D4 + d4], o3);
    }
}

extern "C" void kernel_launch(void* const* d_in, const int* in_sizes, int n_in,
                              void* d_out, int out_size) {
    const float* X    = (const float*)d_in[0];
    const int*   mask = (const int*)d_in[1];
    const float* W    = (const float*)d_in[2];
    const float* bias = (const float*)d_in[3];
    float* out        = (float*)d_out;

    dim3 g1(SPLITS, Bz);
    mn_stats_kernel<<<g1, 256>>>(X, mask);

    dim3 g2(Nz / RPB, Bz);
    mn_norm_kernel<<<g2, 256>>>(X, mask, W, bias, out);
}